// round 12
// baseline (speedup 1.0000x reference)
#include <cuda_runtime.h>
#include <cuda_bf16.h>
#include <cstdint>

// Problem constants (fixed by the dataset)
#define NQ      10880          // total queries = BATCH * tok_per_img
#define TOKB    5440           // valid tokens per image (4096+1024+256+64)
#define EMB     256
#define NHEADS  8
#define HD      32
#define NLEV    4
#define NPTS    4

// Scratch (device globals — no allocation allowed)
__device__ float g_values[2 * TOKB * EMB];      // compact projected values
__device__ float g_offattw[NQ * 384];           // per-query: 256 offsets | 128 attn logits
__device__ __nv_bfloat16 g_qhi[NQ * EMB];       // query split
__device__ __nv_bfloat16 g_qlo[NQ * EMB];
__device__ __nv_bfloat16 g_fhi[NQ * EMB];       // gathered feature-map rows split (compact order)
__device__ __nv_bfloat16 g_flo[NQ * EMB];
__device__ __nv_bfloat16 g_shi[NQ * EMB];       // sampled output split
__device__ __nv_bfloat16 g_slo[NQ * EMB];
// Transposed weights W^T[n,k], rows: [0,256)=W_val, [256,512)=W_off, [512,640)=W_attn, [640,896)=W_out
__device__ __nv_bfloat16 g_wthi[896 * 256];
__device__ __nv_bfloat16 g_wtlo[896 * 256];

__constant__ int c_loff[4] = {0, 4096, 5120, 5376};

// ---------------------------------------------------------------------------
// Warp-MMA helpers (sm_80+ base-target PTX: ldmatrix + mma.sync bf16 + cp.async)
// ---------------------------------------------------------------------------
__device__ __forceinline__ uint32_t smem_u32(const void* p) {
    uint32_t a;
    asm("{ .reg .u64 t; cvta.to.shared.u64 t, %1; cvt.u32.u64 %0, t; }" : "=r"(a) : "l"(p));
    return a;
}
__device__ __forceinline__ void ldsm_x4(uint32_t* r, uint32_t addr) {
    asm volatile("ldmatrix.sync.aligned.m8n8.x4.shared.b16 {%0,%1,%2,%3}, [%4];"
        : "=r"(r[0]), "=r"(r[1]), "=r"(r[2]), "=r"(r[3]) : "r"(addr));
}
__device__ __forceinline__ void mma16816(float* c, const uint32_t* a, const uint32_t* b) {
    asm volatile("mma.sync.aligned.m16n8k16.row.col.f32.bf16.bf16.f32 "
        "{%0,%1,%2,%3}, {%4,%5,%6,%7}, {%8,%9}, {%0,%1,%2,%3};"
        : "+f"(c[0]), "+f"(c[1]), "+f"(c[2]), "+f"(c[3])
        : "r"(a[0]), "r"(a[1]), "r"(a[2]), "r"(a[3]), "r"(b[0]), "r"(b[1]));
}
__device__ __forceinline__ void cp16(uint32_t dst, const void* src) {
    asm volatile("cp.async.cg.shared.global [%0], [%1], 16;" :: "r"(dst), "l"(src));
}
__device__ __forceinline__ void cp_commit() {
    asm volatile("cp.async.commit_group;");
}

// ---------------------------------------------------------------------------
// fm compact-token row decode (float-element offset into feature_maps)
// ---------------------------------------------------------------------------
__device__ __forceinline__ int fm_row_off(int m) {
    int b = (m >= TOKB) ? 1 : 0;
    int r = m - b * TOKB;
    int off;
    if (r < 4096)      { int y = r >> 6,            x = r & 63;          off = (((b*64+y)*64+x)*4+0)*256; }
    else if (r < 5120) { int r2 = r-4096; int y = r2 >> 5, x = r2 & 31;  off = (((b*64+y)*64+x)*4+1)*256; }
    else if (r < 5376) { int r2 = r-5120; int y = r2 >> 4, x = r2 & 15;  off = (((b*64+y)*64+x)*4+2)*256; }
    else               { int r2 = r-5376; int y = r2 >> 3, x = r2 & 7;   off = (((b*64+y)*64+x)*4+3)*256; }
    return off;
}

// split fp32 -> (hi, lo) bf16 pair, store 4 values as one 8B write each
__device__ __forceinline__ void split_store4(float4 v, __nv_bfloat16* hi, __nv_bfloat16* lo, int p) {
    __nv_bfloat16 h0 = __float2bfloat16(v.x), h1 = __float2bfloat16(v.y),
                  h2 = __float2bfloat16(v.z), h3 = __float2bfloat16(v.w);
    __nv_bfloat16 l0 = __float2bfloat16(v.x - __bfloat162float(h0));
    __nv_bfloat16 l1 = __float2bfloat16(v.y - __bfloat162float(h1));
    __nv_bfloat16 l2 = __float2bfloat16(v.z - __bfloat162float(h2));
    __nv_bfloat16 l3 = __float2bfloat16(v.w - __bfloat162float(h3));
    union { __nv_bfloat162 b[2]; uint2 u; } uh, ul;
    uh.b[0].x = h0; uh.b[0].y = h1; uh.b[1].x = h2; uh.b[1].y = h3;
    ul.b[0].x = l0; ul.b[0].y = l1; ul.b[1].x = l2; ul.b[1].y = l3;
    *reinterpret_cast<uint2*>(hi + p) = uh.u;
    *reinterpret_cast<uint2*>(lo + p) = ul.u;
}

// ---------------------------------------------------------------------------
// Fused split kernel: fp32 -> bf16 hi/lo for query, gathered fm rows, weights
// blocks [0, NB_IN)          : query + fm rows  (NQ*64 threads)
// blocks [NB_IN, NB_IN+896)  : transposed weights (896*256 threads)
// ---------------------------------------------------------------------------
#define NB_IN (NQ * 64 / 256)

__global__ void __launch_bounds__(256) split_all_kernel(
    const float* __restrict__ query, const float* __restrict__ fm,
    const float* __restrict__ W_val, const float* __restrict__ W_off,
    const float* __restrict__ W_attn, const float* __restrict__ W_out)
{
    if (blockIdx.x < NB_IN) {
        int idx = blockIdx.x * 256 + threadIdx.x;
        int m  = idx >> 6;
        int k4 = (idx & 63) << 2;
        float4 qv = *reinterpret_cast<const float4*>(query + m * EMB + k4);
        split_store4(qv, g_qhi, g_qlo, m * EMB + k4);
        float4 fv = *reinterpret_cast<const float4*>(fm + fm_row_off(m) + k4);
        split_store4(fv, g_fhi, g_flo, m * EMB + k4);
    } else {
        int idx = (blockIdx.x - NB_IN) * 256 + threadIdx.x;
        int row = idx >> 8, k = idx & 255;
        const float* src; int n, NB;
        if (row < 256)      { src = W_val;  n = row;       NB = 256; }
        else if (row < 512) { src = W_off;  n = row - 256; NB = 256; }
        else if (row < 640) { src = W_attn; n = row - 512; NB = 128; }
        else                { src = W_out;  n = row - 640; NB = 256; }
        float v = src[k * NB + n];
        __nv_bfloat16 h = __float2bfloat16(v);
        g_wthi[row * 256 + k] = h;
        g_wtlo[row * 256 + k] = __float2bfloat16(v - __bfloat162float(h));
    }
}

// ---------------------------------------------------------------------------
// Warp-MMA tile: C[128,128] = A[128,256](hi+lo) @ B(128 W^T rows)(hi+lo) + bias
// Split-fp32: Ahi*Bhi + Ahi*Blo + Alo*Bhi, fp32 accumulate in registers.
// 8 warps as 4(m) x 2(n): each warp 32m x 64n.
// K staged 32/chunk; each 128B smem row = [hi 64B | lo 64B] (SW128 swizzle,
// conflict-free ldmatrix). 2-stage cp.async double buffer, 32KB/stage,
// 64KB total -> 2 CTAs/SM.
// ---------------------------------------------------------------------------
#define SA_OFF 0
#define SB_OFF 16384
#define STAGE_SZ 32768
#define SM_TOT (2 * STAGE_SZ)

__device__ __forceinline__ void mma_tile128(
    const __nv_bfloat16* __restrict__ Ahi, const __nv_bfloat16* __restrict__ Alo,
    const __nv_bfloat16* __restrict__ Bhi, const __nv_bfloat16* __restrict__ Blo,
    const float* __restrict__ bias, float* __restrict__ C,
    int ldc, int cbase, int m0)
{
    extern __shared__ char smem[];
    const uint32_t sb = smem_u32(smem);
    const int tid = threadIdx.x;
    const int wid = tid >> 5, lane = tid & 31;
    const int warp_m = wid & 3, warp_n = wid >> 2;
    const int grp = lane >> 3, l8 = lane & 7;

    float acc[2][8][4];
    #pragma unroll
    for (int mi = 0; mi < 2; ++mi)
        #pragma unroll
        for (int ni = 0; ni < 8; ++ni)
            #pragma unroll
            for (int j = 0; j < 4; ++j) acc[mi][ni][j] = 0.0f;

    // staging: 2 threads per row; even thread -> A row, odd thread -> B row.
    // Row layout (128B): [hi 64B | lo 64B], SW128 swizzle.
    const int  lr  = tid >> 1;
    const bool isB = tid & 1;
    const char* pH = isB ? reinterpret_cast<const char*>(Bhi + lr * 256)
                         : reinterpret_cast<const char*>(Ahi + (m0 + lr) * 256);
    const char* pL = isB ? reinterpret_cast<const char*>(Blo + lr * 256)
                         : reinterpret_cast<const char*>(Alo + (m0 + lr) * 256);
    const uint32_t mat_off = isB ? SB_OFF : SA_OFF;

    uint32_t dsto[8];
    #pragma unroll
    for (int u = 0; u < 8; ++u) {
        uint32_t bo = lr * 128 + u * 16;
        dsto[u] = mat_off + (bo ^ ((bo >> 3) & 0x70));
    }

    // fragment-load address bases
    const int a_row = warp_m * 32 + (grp & 1) * 8 + l8;     // + mi*16
    const int a_kb0 = (grp >> 1) * 16;                      // within 64B hi half
    const int b_row = warp_n * 64 + (grp >> 1) * 8 + l8;    // + pi*16
    const int b_kb0 = (grp & 1) * 16;

    // ---- issue stage for K-chunk kc (32 k-values = 64B per source row)
    #define ISSUE(kc) do { \
        uint32_t sbase = sb + ((kc) & 1) * STAGE_SZ; \
        int gb = (kc) * 64; \
        _Pragma("unroll") \
        for (int u = 0; u < 4; ++u) \
            cp16(sbase + dsto[u], pH + gb + u * 16); \
        _Pragma("unroll") \
        for (int u = 4; u < 8; ++u) \
            cp16(sbase + dsto[u], pL + gb + (u - 4) * 16); \
        cp_commit(); \
    } while (0)

    ISSUE(0);

    for (int kc = 0; kc < 8; ++kc) {
        if (kc < 7) ISSUE(kc + 1);
        if (kc < 7) asm volatile("cp.async.wait_group 1;");
        else        asm volatile("cp.async.wait_group 0;");
        __syncthreads();

        const uint32_t stg = sb + (kc & 1) * STAGE_SZ;
        #pragma unroll
        for (int s = 0; s < 2; ++s) {
            const int kb = s * 32;
            uint32_t ah[2][4], al[2][4];
            #pragma unroll
            for (int mi = 0; mi < 2; ++mi) {
                uint32_t off = (a_row + mi * 16) * 128 + kb + a_kb0;
                uint32_t soh = off ^ ((off >> 3) & 0x70);
                uint32_t ofl = off + 64;
                uint32_t sol = ofl ^ ((ofl >> 3) & 0x70);
                ldsm_x4(ah[mi], stg + SA_OFF + soh);
                ldsm_x4(al[mi], stg + SA_OFF + sol);
            }
            uint32_t bh[4][4], bl[4][4];
            #pragma unroll
            for (int pi = 0; pi < 4; ++pi) {
                uint32_t off = (b_row + pi * 16) * 128 + kb + b_kb0;
                uint32_t soh = off ^ ((off >> 3) & 0x70);
                uint32_t ofl = off + 64;
                uint32_t sol = ofl ^ ((ofl >> 3) & 0x70);
                ldsm_x4(bh[pi], stg + SB_OFF + soh);
                ldsm_x4(bl[pi], stg + SB_OFF + sol);
            }
            #pragma unroll
            for (int mi = 0; mi < 2; ++mi)
                #pragma unroll
                for (int pi = 0; pi < 4; ++pi)
                    #pragma unroll
                    for (int hf = 0; hf < 2; ++hf) {
                        float* c = acc[mi][pi * 2 + hf];
                        mma16816(c, ah[mi], &bh[pi][hf * 2]);
                        mma16816(c, ah[mi], &bl[pi][hf * 2]);
                        mma16816(c, al[mi], &bh[pi][hf * 2]);
                    }
        }
        __syncthreads();
    }
    #undef ISSUE

    // ---- epilogue: accumulators -> C (+bias)
    const int rbase = m0 + warp_m * 32 + (lane >> 2);
    const int nc0   = warp_n * 64 + (lane & 3) * 2;
    #pragma unroll
    for (int mi = 0; mi < 2; ++mi) {
        #pragma unroll
        for (int ni = 0; ni < 8; ++ni) {
            int nl = nc0 + ni * 8;
            float b0 = bias[nl], b1 = bias[nl + 1];
            const float* c = acc[mi][ni];
            int r0 = rbase + mi * 16;
            float2 v0 = {c[0] + b0, c[1] + b1};
            float2 v1 = {c[2] + b0, c[3] + b1};
            *reinterpret_cast<float2*>(C + (size_t)r0 * ldc + cbase + nl) = v0;
            *reinterpret_cast<float2*>(C + (size_t)(r0 + 8) * ldc + cbase + nl) = v1;
        }
    }
}

// Fused input-side MMAs: y=0,1 values halves; y=2,3 offsets halves; y=4 attn logits
__global__ void __launch_bounds__(256, 2) mma_fused_kernel(
    const float* __restrict__ b_val, const float* __restrict__ b_off,
    const float* __restrict__ b_attn)
{
    const int m0 = blockIdx.x * 128;
    const int y  = blockIdx.y;
    switch (y) {
    case 0: mma_tile128(g_fhi, g_flo, g_wthi +   0*256, g_wtlo +   0*256, b_val,       g_values,  256,   0, m0); break;
    case 1: mma_tile128(g_fhi, g_flo, g_wthi + 128*256, g_wtlo + 128*256, b_val + 128, g_values,  256, 128, m0); break;
    case 2: mma_tile128(g_qhi, g_qlo, g_wthi + 256*256, g_wtlo + 256*256, b_off,       g_offattw, 384,   0, m0); break;
    case 3: mma_tile128(g_qhi, g_qlo, g_wthi + 384*256, g_wtlo + 384*256, b_off + 128, g_offattw, 384, 128, m0); break;
    default:mma_tile128(g_qhi, g_qlo, g_wthi + 512*256, g_wtlo + 512*256, b_attn,      g_offattw, 384, 256, m0); break;
    }
}

// Output projection MMA: d_out = attn_out @ W_out + b_out
__global__ void __launch_bounds__(256, 2) mma_out_kernel(
    const float* __restrict__ b_out, float* __restrict__ out)
{
    const int m0 = blockIdx.x * 128;
    const int nh = blockIdx.y;
    mma_tile128(g_shi, g_slo, g_wthi + (640 + nh*128)*256, g_wtlo + (640 + nh*128)*256,
                b_out + nh*128, out, 256, nh*128, m0);
}

// ---------------------------------------------------------------------------
// Sampling (vectorized 4x): block = 256 threads = 4 queries x 64 threads.
// Per query: 8 heads x 8 lanes; each lane owns 4 channels (float4 gathers).
// Writes the result pre-split to bf16 hi/lo for the out-projection MMA.
// min-blocks 7 -> ~36 regs -> ~88% occupancy (latency-bound kernel).
// ---------------------------------------------------------------------------
__global__ void __launch_bounds__(256, 7) sample_kernel(
    const float* __restrict__ qpos,
    const int*   __restrict__ qlvl,
    const int*   __restrict__ qbo)
{
    const int tid = threadIdx.x;
    const int q0  = blockIdx.x * 4;
    const int qi  = tid >> 6;            // query slot in block (0..3)
    const int q   = q0 + qi;
    const int tq  = tid & 63;            // thread within query
    const int h   = tq >> 3;             // head (0..7)
    const int lg  = tq & 7;              // lane in head group; channels lg*4..lg*4+3

    __shared__ float s_scaled[4][NLEV][2];
    __shared__ int   s_b[4];

    if (tid < 32) {
        int qi2 = tid >> 3, idx = tid & 7;
        int l = idx >> 1, c = idx & 1;
        int qq = q0 + qi2;
        int ql = qlvl[qq];
        float shp_q = (float)(64 >> ql);
        float shp_l = (float)(64 >> l);
        s_scaled[qi2][l][c] = (qpos[qq * 2 + c] / shp_q) * shp_l;
    }
    if (tid < 4) {
        s_b[tid] = (qbo[1] <= q0 + tid) ? 1 : 0;
    }
    __syncthreads();

    const float* oa = g_offattw + q * 384;

    // softmax over 16 logits of this head: 2 logits per lane, width-8 segments
    float a0 = oa[256 + lg * 16 + h];
    float a1 = oa[256 + lg * 16 + 8 + h];
    float mx = fmaxf(a0, a1);
    #pragma unroll
    for (int j = 4; j >= 1; j >>= 1) mx = fmaxf(mx, __shfl_xor_sync(0xffffffffu, mx, j, 8));
    float e0 = __expf(a0 - mx);
    float e1 = __expf(a1 - mx);
    float s = e0 + e1;
    #pragma unroll
    for (int j = 4; j >= 1; j >>= 1) s += __shfl_xor_sync(0xffffffffu, s, j, 8);
    float inv = __frcp_rn(s);
    float w0 = e0 * inv;
    float w1 = e1 * inv;

    float2 off_a = *reinterpret_cast<const float2*>(oa + (lg * 16 + h) * 2);
    float2 off_b = *reinterpret_cast<const float2*>(oa + (lg * 16 + 8 + h) * 2);

    const int b = s_b[qi];
    const int base = (b * TOKB) * EMB + h * HD + lg * 4;
    float4 acc = {0.0f, 0.0f, 0.0f, 0.0f};
    const float4 zero = {0.0f, 0.0f, 0.0f, 0.0f};

    #pragma unroll
    for (int l = 0; l < NLEV; ++l) {
        const int   sh = 6 - l;
        const int   Wl = 64 >> l;
        const float Hf = (float)Wl;
        const float sc_h = s_scaled[qi][l][0];
        const float sc_w = s_scaled[qi][l][1];
        const float* vb = g_values + base + c_loff[l] * EMB;
        const int rowStep = Wl << 8;

        #pragma unroll
        for (int p = 0; p < NPTS; ++p) {
            const int i = p * NLEV + l;
            float offh = __shfl_sync(0xffffffffu, (i & 1) ? off_b.x : off_a.x, i >> 1, 8);
            float offw = __shfl_sync(0xffffffffu, (i & 1) ? off_b.y : off_a.y, i >> 1, 8);
            float aw   = __shfl_sync(0xffffffffu, (i & 1) ? w1     : w0,      i >> 1, 8);

            float hf = fminf(fmaxf(sc_h + offh, 0.0f), Hf);
            float wf = fminf(fmaxf(sc_w + offw, 0.0f), Hf);
            float h0f = floorf(hf), w0f = floorf(wf);
            float fh = hf - h0f,    fw = wf - w0f;
            int h0 = (int)h0f, w0i = (int)w0f;

            bool h0ok = h0 < Wl;
            bool h1ok = (h0 + 1) < Wl;
            bool w0ok = w0i < Wl;
            bool w1ok = (w0i + 1) < Wl;

            int idx = ((h0 << sh) + w0i) << 8;

            float4 v00 = (h0ok && w0ok) ? *reinterpret_cast<const float4*>(vb + idx)                 : zero;
            float4 v01 = (h0ok && w1ok) ? *reinterpret_cast<const float4*>(vb + idx + EMB)           : zero;
            float4 v10 = (h1ok && w0ok) ? *reinterpret_cast<const float4*>(vb + idx + rowStep)       : zero;
            float4 v11 = (h1ok && w1ok) ? *reinterpret_cast<const float4*>(vb + idx + rowStep + EMB) : zero;

            float4 top, bot;
            top.x = v00.x + fw * (v01.x - v00.x);
            top.y = v00.y + fw * (v01.y - v00.y);
            top.z = v00.z + fw * (v01.z - v00.z);
            top.w = v00.w + fw * (v01.w - v00.w);
            bot.x = v10.x + fw * (v11.x - v10.x);
            bot.y = v10.y + fw * (v11.y - v10.y);
            bot.z = v10.z + fw * (v11.z - v10.z);
            bot.w = v10.w + fw * (v11.w - v10.w);
            acc.x += aw * (top.x + fh * (bot.x - top.x));
            acc.y += aw * (top.y + fh * (bot.y - top.y));
            acc.z += aw * (top.z + fh * (bot.z - top.z));
            acc.w += aw * (top.w + fh * (bot.w - top.w));
        }
    }

    split_store4(acc, g_shi, g_slo, q * EMB + h * HD + lg * 4);
}

// ---------------------------------------------------------------------------
extern "C" void kernel_launch(void* const* d_in, const int* in_sizes, int n_in,
                              void* d_out, int out_size)
{
    const float* query  = (const float*)d_in[0];
    const float* qpos   = (const float*)d_in[1];
    const int*   qbo    = (const int*)  d_in[2];
    const float* fm     = (const float*)d_in[3];
    // d_in[4] = level_spatial_shapes (compile-time constants here)
    const int*   qlvl   = (const int*)  d_in[5];
    const float* W_off  = (const float*)d_in[6];
    const float* b_off  = (const float*)d_in[7];
    const float* W_attn = (const float*)d_in[8];
    const float* b_attn = (const float*)d_in[9];
    const float* W_val  = (const float*)d_in[10];
    const float* b_val  = (const float*)d_in[11];
    const float* W_out  = (const float*)d_in[12];
    const float* b_out  = (const float*)d_in[13];
    float* out = (float*)d_out;

    cudaFuncSetAttribute(mma_fused_kernel, cudaFuncAttributeMaxDynamicSharedMemorySize, SM_TOT);
    cudaFuncSetAttribute(mma_out_kernel,   cudaFuncAttributeMaxDynamicSharedMemorySize, SM_TOT);

    // 1) fp32 -> bf16 hi/lo splits (query, gathered fm rows, transposed weights)
    split_all_kernel<<<NB_IN + 896, 256>>>(query, fm, W_val, W_off, W_attn, W_out);
    // 2) tensor-core MMAs: values projection + offsets + attn logits
    mma_fused_kernel<<<dim3(NQ / 128, 5), 256, SM_TOT>>>(b_val, b_off, b_attn);
    // 3) softmax + bilinear sampling + head-weighted accumulation (writes split)
    sample_kernel<<<NQ / 4, 256>>>(qpos, qlvl, qbo);
    // 4) output projection MMA -> d_out
    mma_out_kernel<<<dim3(NQ / 128, 2), 256, SM_TOT>>>(b_out, out);
}

// round 17
// speedup vs baseline: 1.2361x; 1.2361x over previous
#include <cuda_runtime.h>
#include <cuda_bf16.h>
#include <cstdint>

// Problem constants (fixed by the dataset)
#define NQ      10880          // total queries = BATCH * tok_per_img
#define TOKB    5440           // valid tokens per image (4096+1024+256+64)
#define EMB     256
#define NHEADS  8
#define HD      32
#define NLEV    4
#define NPTS    4

// Scratch (device globals — no allocation allowed)
__device__ float g_values[2 * TOKB * EMB];      // compact projected values
__device__ float g_offattw[NQ * 384];           // per-query: 256 offsets | 128 attn logits
__device__ __nv_bfloat16 g_qhi[NQ * EMB];       // query split
__device__ __nv_bfloat16 g_qlo[NQ * EMB];
__device__ __nv_bfloat16 g_fhi[NQ * EMB];       // gathered feature-map rows split (compact order)
__device__ __nv_bfloat16 g_flo[NQ * EMB];
__device__ __nv_bfloat16 g_shi[NQ * EMB];       // sampled output split
__device__ __nv_bfloat16 g_slo[NQ * EMB];
// Transposed weights W^T[n,k], rows: [0,256)=W_val, [256,512)=W_off, [512,640)=W_attn, [640,896)=W_out
__device__ __nv_bfloat16 g_wthi[896 * 256];
__device__ __nv_bfloat16 g_wtlo[896 * 256];

__constant__ int c_loff[4] = {0, 4096, 5120, 5376};

// ---------------------------------------------------------------------------
// Warp-MMA helpers (sm_80+ base-target PTX: ldmatrix + mma.sync bf16 + cp.async)
// ---------------------------------------------------------------------------
__device__ __forceinline__ uint32_t smem_u32(const void* p) {
    uint32_t a;
    asm("{ .reg .u64 t; cvta.to.shared.u64 t, %1; cvt.u32.u64 %0, t; }" : "=r"(a) : "l"(p));
    return a;
}
__device__ __forceinline__ void ldsm_x4(uint32_t* r, uint32_t addr) {
    asm volatile("ldmatrix.sync.aligned.m8n8.x4.shared.b16 {%0,%1,%2,%3}, [%4];"
        : "=r"(r[0]), "=r"(r[1]), "=r"(r[2]), "=r"(r[3]) : "r"(addr));
}
__device__ __forceinline__ void mma16816(float* c, const uint32_t* a, const uint32_t* b) {
    asm volatile("mma.sync.aligned.m16n8k16.row.col.f32.bf16.bf16.f32 "
        "{%0,%1,%2,%3}, {%4,%5,%6,%7}, {%8,%9}, {%0,%1,%2,%3};"
        : "+f"(c[0]), "+f"(c[1]), "+f"(c[2]), "+f"(c[3])
        : "r"(a[0]), "r"(a[1]), "r"(a[2]), "r"(a[3]), "r"(b[0]), "r"(b[1]));
}
__device__ __forceinline__ void cp16(uint32_t dst, const void* src) {
    asm volatile("cp.async.cg.shared.global [%0], [%1], 16;" :: "r"(dst), "l"(src));
}
__device__ __forceinline__ void cp_commit() {
    asm volatile("cp.async.commit_group;");
}

// ---------------------------------------------------------------------------
// fm compact-token row decode (float-element offset into feature_maps)
// ---------------------------------------------------------------------------
__device__ __forceinline__ int fm_row_off(int m) {
    int b = (m >= TOKB) ? 1 : 0;
    int r = m - b * TOKB;
    int off;
    if (r < 4096)      { int y = r >> 6,            x = r & 63;          off = (((b*64+y)*64+x)*4+0)*256; }
    else if (r < 5120) { int r2 = r-4096; int y = r2 >> 5, x = r2 & 31;  off = (((b*64+y)*64+x)*4+1)*256; }
    else if (r < 5376) { int r2 = r-5120; int y = r2 >> 4, x = r2 & 15;  off = (((b*64+y)*64+x)*4+2)*256; }
    else               { int r2 = r-5376; int y = r2 >> 3, x = r2 & 7;   off = (((b*64+y)*64+x)*4+3)*256; }
    return off;
}

// split fp32 -> (hi, lo) bf16 pair, store 4 values as one 8B write each
__device__ __forceinline__ void split_store4(float4 v, __nv_bfloat16* hi, __nv_bfloat16* lo, int p) {
    __nv_bfloat16 h0 = __float2bfloat16(v.x), h1 = __float2bfloat16(v.y),
                  h2 = __float2bfloat16(v.z), h3 = __float2bfloat16(v.w);
    __nv_bfloat16 l0 = __float2bfloat16(v.x - __bfloat162float(h0));
    __nv_bfloat16 l1 = __float2bfloat16(v.y - __bfloat162float(h1));
    __nv_bfloat16 l2 = __float2bfloat16(v.z - __bfloat162float(h2));
    __nv_bfloat16 l3 = __float2bfloat16(v.w - __bfloat162float(h3));
    union { __nv_bfloat162 b[2]; uint2 u; } uh, ul;
    uh.b[0].x = h0; uh.b[0].y = h1; uh.b[1].x = h2; uh.b[1].y = h3;
    ul.b[0].x = l0; ul.b[0].y = l1; ul.b[1].x = l2; ul.b[1].y = l3;
    *reinterpret_cast<uint2*>(hi + p) = uh.u;
    *reinterpret_cast<uint2*>(lo + p) = ul.u;
}

// ---------------------------------------------------------------------------
// Fused split kernel: fp32 -> bf16 hi/lo for query, gathered fm rows, weights
// blocks [0, NB_IN)          : query + fm rows  (NQ*64 threads)
// blocks [NB_IN, NB_IN+896)  : transposed weights (896*256 threads)
// ---------------------------------------------------------------------------
#define NB_IN (NQ * 64 / 256)

__global__ void __launch_bounds__(256) split_all_kernel(
    const float* __restrict__ query, const float* __restrict__ fm,
    const float* __restrict__ W_val, const float* __restrict__ W_off,
    const float* __restrict__ W_attn, const float* __restrict__ W_out)
{
    if (blockIdx.x < NB_IN) {
        int idx = blockIdx.x * 256 + threadIdx.x;
        int m  = idx >> 6;
        int k4 = (idx & 63) << 2;
        float4 qv = *reinterpret_cast<const float4*>(query + m * EMB + k4);
        split_store4(qv, g_qhi, g_qlo, m * EMB + k4);
        float4 fv = *reinterpret_cast<const float4*>(fm + fm_row_off(m) + k4);
        split_store4(fv, g_fhi, g_flo, m * EMB + k4);
    } else {
        int idx = (blockIdx.x - NB_IN) * 256 + threadIdx.x;
        int row = idx >> 8, k = idx & 255;
        const float* src; int n, NB;
        if (row < 256)      { src = W_val;  n = row;       NB = 256; }
        else if (row < 512) { src = W_off;  n = row - 256; NB = 256; }
        else if (row < 640) { src = W_attn; n = row - 512; NB = 128; }
        else                { src = W_out;  n = row - 640; NB = 256; }
        float v = src[k * NB + n];
        __nv_bfloat16 h = __float2bfloat16(v);
        g_wthi[row * 256 + k] = h;
        g_wtlo[row * 256 + k] = __float2bfloat16(v - __bfloat162float(h));
    }
}

// ---------------------------------------------------------------------------
// Warp-MMA tile: C[128,64] = A[128,256](hi+lo) @ B(64 W^T rows)(hi+lo) + bias
// Split-fp32: Ahi*Bhi + Ahi*Blo + Alo*Bhi, fp32 accumulate in registers.
// 8 warps as 4(m) x 2(n): each warp 32m x 32n. K staged 64/chunk (R10-proven
// structure: 192 MMAs between barriers), 2-stage cp.async double buffer.
// Stage = 48KB (A 32K + B 16K); 96KB total -> 2 CTAs/SM.
// ---------------------------------------------------------------------------
#define SA_HI 0
#define SA_LO 16384
#define SB_HI 32768
#define SB_LO 40960
#define STAGE_SZ 49152
#define SM_TOT (2 * STAGE_SZ)

__device__ __forceinline__ void mma_tile(
    const __nv_bfloat16* __restrict__ Ahi, const __nv_bfloat16* __restrict__ Alo,
    const __nv_bfloat16* __restrict__ Bhi, const __nv_bfloat16* __restrict__ Blo,
    const float* __restrict__ bias, float* __restrict__ C,
    int ldc, int cbase, int m0)
{
    extern __shared__ char smem[];
    const uint32_t sb = smem_u32(smem);
    const int tid = threadIdx.x;
    const int wid = tid >> 5, lane = tid & 31;
    const int warp_m = wid & 3, warp_n = wid >> 2;
    const int grp = lane >> 3, l8 = lane & 7;

    float acc[2][4][4];
    #pragma unroll
    for (int mi = 0; mi < 2; ++mi)
        #pragma unroll
        for (int ni = 0; ni < 4; ++ni)
            #pragma unroll
            for (int j = 0; j < 4; ++j) acc[mi][ni][j] = 0.0f;

    // A staging: all 256 threads, 2 per row (rows 0..127), 4 chunks hi + 4 lo
    const int lr  = tid >> 1;
    const int lc0 = (tid & 1) * 4;
    const char* pAh = reinterpret_cast<const char*>(Ahi + (m0 + lr) * 256);
    const char* pAl = reinterpret_cast<const char*>(Alo + (m0 + lr) * 256);
    uint32_t dstA[4];
    #pragma unroll
    for (int u = 0; u < 4; ++u) {
        uint32_t bo = lr * 128 + (lc0 + u) * 16;
        dstA[u] = bo ^ ((bo >> 3) & 0x70);
    }
    // B staging: threads 0..127, 2 per row (rows 0..63), 4 chunks hi + 4 lo
    const bool doB = tid < 128;
    const int lrB = tid >> 1;              // 0..63 when doB
    const char* pBh = reinterpret_cast<const char*>(Bhi + lrB * 256);
    const char* pBl = reinterpret_cast<const char*>(Blo + lrB * 256);
    uint32_t dstB[4];
    #pragma unroll
    for (int u = 0; u < 4; ++u) {
        uint32_t bo = lrB * 128 + (lc0 + u) * 16;
        dstB[u] = bo ^ ((bo >> 3) & 0x70);
    }

    // fragment-load address bases
    const int a_row = warp_m * 32 + (grp & 1) * 8 + l8;     // + mi*16
    const int a_kb0 = (grp >> 1) * 16;
    const int b_row = warp_n * 32 + (grp >> 1) * 8 + l8;    // + pi*16
    const int b_kb0 = (grp & 1) * 16;

    // ---- issue stage for K-chunk kc (64 k-values = 128B per source row)
    #define ISSUE(kc) do { \
        uint32_t sbase = sb + ((kc) & 1) * STAGE_SZ; \
        int gb = (kc) * 128; \
        _Pragma("unroll") \
        for (int u = 0; u < 4; ++u) { \
            int co = (lc0 + u) * 16; \
            cp16(sbase + SA_HI + dstA[u], pAh + gb + co); \
            cp16(sbase + SA_LO + dstA[u], pAl + gb + co); \
        } \
        if (doB) { \
            _Pragma("unroll") \
            for (int u = 0; u < 4; ++u) { \
                int co = (lc0 + u) * 16; \
                cp16(sbase + SB_HI + dstB[u], pBh + gb + co); \
                cp16(sbase + SB_LO + dstB[u], pBl + gb + co); \
            } \
        } \
        cp_commit(); \
    } while (0)

    ISSUE(0);

    for (int kc = 0; kc < 4; ++kc) {
        if (kc < 3) ISSUE(kc + 1);
        if (kc < 3) asm volatile("cp.async.wait_group 1;");
        else        asm volatile("cp.async.wait_group 0;");
        __syncthreads();

        const uint32_t stg = sb + (kc & 1) * STAGE_SZ;
        #pragma unroll
        for (int s = 0; s < 4; ++s) {
            const int kb = s * 32;
            uint32_t ah[2][4], al[2][4];
            #pragma unroll
            for (int mi = 0; mi < 2; ++mi) {
                uint32_t off = (a_row + mi * 16) * 128 + kb + a_kb0;
                uint32_t so = off ^ ((off >> 3) & 0x70);
                ldsm_x4(ah[mi], stg + SA_HI + so);
                ldsm_x4(al[mi], stg + SA_LO + so);
            }
            uint32_t bh[2][4], bl[2][4];
            #pragma unroll
            for (int pi = 0; pi < 2; ++pi) {
                uint32_t off = (b_row + pi * 16) * 128 + kb + b_kb0;
                uint32_t so = off ^ ((off >> 3) & 0x70);
                ldsm_x4(bh[pi], stg + SB_HI + so);
                ldsm_x4(bl[pi], stg + SB_LO + so);
            }
            #pragma unroll
            for (int mi = 0; mi < 2; ++mi)
                #pragma unroll
                for (int pi = 0; pi < 2; ++pi)
                    #pragma unroll
                    for (int hf = 0; hf < 2; ++hf) {
                        float* c = acc[mi][pi * 2 + hf];
                        mma16816(c, ah[mi], &bh[pi][hf * 2]);
                        mma16816(c, ah[mi], &bl[pi][hf * 2]);
                        mma16816(c, al[mi], &bh[pi][hf * 2]);
                    }
        }
        __syncthreads();
    }
    #undef ISSUE

    // ---- epilogue: accumulators -> C (+bias)
    const int rbase = m0 + warp_m * 32 + (lane >> 2);
    const int nc0   = warp_n * 32 + (lane & 3) * 2;
    #pragma unroll
    for (int mi = 0; mi < 2; ++mi) {
        #pragma unroll
        for (int ni = 0; ni < 4; ++ni) {
            int nl = nc0 + ni * 8;
            float b0 = bias[nl], b1 = bias[nl + 1];
            const float* c = acc[mi][ni];
            int r0 = rbase + mi * 16;
            float2 v0 = {c[0] + b0, c[1] + b1};
            float2 v1 = {c[2] + b0, c[3] + b1};
            *reinterpret_cast<float2*>(C + (size_t)r0 * ldc + cbase + nl) = v0;
            *reinterpret_cast<float2*>(C + (size_t)(r0 + 8) * ldc + cbase + nl) = v1;
        }
    }
}

// Fused input-side MMAs, N-sliced by 64:
//  y 0..3 : values slice    -> g_values  cols [y*64, y*64+64)
//  y 4..7 : offsets slice   -> g_offattw cols [s*64, s*64+64)
//  y 8..9 : attn logits     -> g_offattw cols [256+s*64, ...)
__global__ void __launch_bounds__(256, 2) mma_fused_kernel(
    const float* __restrict__ b_val, const float* __restrict__ b_off,
    const float* __restrict__ b_attn)
{
    const int m0 = blockIdx.x * 128;
    const int y  = blockIdx.y;
    if (y < 4) {
        mma_tile(g_fhi, g_flo, g_wthi + y*64*256, g_wtlo + y*64*256,
                 b_val + y*64, g_values, 256, y*64, m0);
    } else if (y < 8) {
        int s = y - 4;
        mma_tile(g_qhi, g_qlo, g_wthi + (256 + s*64)*256, g_wtlo + (256 + s*64)*256,
                 b_off + s*64, g_offattw, 384, s*64, m0);
    } else {
        int s = y - 8;
        mma_tile(g_qhi, g_qlo, g_wthi + (512 + s*64)*256, g_wtlo + (512 + s*64)*256,
                 b_attn + s*64, g_offattw, 384, 256 + s*64, m0);
    }
}

// Output projection MMA: d_out = attn_out @ W_out + b_out (N-sliced by 64)
__global__ void __launch_bounds__(256, 2) mma_out_kernel(
    const float* __restrict__ b_out, float* __restrict__ out)
{
    const int m0 = blockIdx.x * 128;
    const int s  = blockIdx.y;
    mma_tile(g_shi, g_slo, g_wthi + (640 + s*64)*256, g_wtlo + (640 + s*64)*256,
             b_out + s*64, out, 256, s*64, m0);
}

// ---------------------------------------------------------------------------
// Sampling (vectorized 4x): block = 256 threads = 4 queries x 64 threads.
// Per query: 8 heads x 8 lanes; each lane owns 4 channels (float4 gathers).
// Writes the result pre-split to bf16 hi/lo for the out-projection MMA.
// ---------------------------------------------------------------------------
__global__ void __launch_bounds__(256, 6) sample_kernel(
    const float* __restrict__ qpos,
    const int*   __restrict__ qlvl,
    const int*   __restrict__ qbo)
{
    const int tid = threadIdx.x;
    const int q0  = blockIdx.x * 4;
    const int qi  = tid >> 6;            // query slot in block (0..3)
    const int q   = q0 + qi;
    const int tq  = tid & 63;            // thread within query
    const int h   = tq >> 3;             // head (0..7)
    const int lg  = tq & 7;              // lane in head group; channels lg*4..lg*4+3

    __shared__ float s_scaled[4][NLEV][2];
    __shared__ int   s_b[4];

    if (tid < 32) {
        int qi2 = tid >> 3, idx = tid & 7;
        int l = idx >> 1, c = idx & 1;
        int qq = q0 + qi2;
        int ql = qlvl[qq];
        float shp_q = (float)(64 >> ql);
        float shp_l = (float)(64 >> l);
        s_scaled[qi2][l][c] = (qpos[qq * 2 + c] / shp_q) * shp_l;
    }
    if (tid < 4) {
        s_b[tid] = (qbo[1] <= q0 + tid) ? 1 : 0;
    }
    __syncthreads();

    const float* oa = g_offattw + q * 384;

    // softmax over 16 logits of this head: 2 logits per lane, width-8 segments
    float a0 = oa[256 + lg * 16 + h];
    float a1 = oa[256 + lg * 16 + 8 + h];
    float mx = fmaxf(a0, a1);
    #pragma unroll
    for (int j = 4; j >= 1; j >>= 1) mx = fmaxf(mx, __shfl_xor_sync(0xffffffffu, mx, j, 8));
    float e0 = __expf(a0 - mx);
    float e1 = __expf(a1 - mx);
    float s = e0 + e1;
    #pragma unroll
    for (int j = 4; j >= 1; j >>= 1) s += __shfl_xor_sync(0xffffffffu, s, j, 8);
    float inv = __frcp_rn(s);
    float w0 = e0 * inv;
    float w1 = e1 * inv;

    float2 off_a = *reinterpret_cast<const float2*>(oa + (lg * 16 + h) * 2);
    float2 off_b = *reinterpret_cast<const float2*>(oa + (lg * 16 + 8 + h) * 2);

    const int b = s_b[qi];
    const int base = (b * TOKB) * EMB + h * HD + lg * 4;
    float4 acc = {0.0f, 0.0f, 0.0f, 0.0f};
    const float4 zero = {0.0f, 0.0f, 0.0f, 0.0f};

    #pragma unroll
    for (int l = 0; l < NLEV; ++l) {
        const int   sh = 6 - l;
        const int   Wl = 64 >> l;
        const float Hf = (float)Wl;
        const float sc_h = s_scaled[qi][l][0];
        const float sc_w = s_scaled[qi][l][1];
        const float* vb = g_values + base + c_loff[l] * EMB;
        const int rowStep = Wl << 8;

        #pragma unroll
        for (int p = 0; p < NPTS; ++p) {
            const int i = p * NLEV + l;
            float offh = __shfl_sync(0xffffffffu, (i & 1) ? off_b.x : off_a.x, i >> 1, 8);
            float offw = __shfl_sync(0xffffffffu, (i & 1) ? off_b.y : off_a.y, i >> 1, 8);
            float aw   = __shfl_sync(0xffffffffu, (i & 1) ? w1     : w0,      i >> 1, 8);

            float hf = fminf(fmaxf(sc_h + offh, 0.0f), Hf);
            float wf = fminf(fmaxf(sc_w + offw, 0.0f), Hf);
            float h0f = floorf(hf), w0f = floorf(wf);
            float fh = hf - h0f,    fw = wf - w0f;
            int h0 = (int)h0f, w0i = (int)w0f;

            bool h0ok = h0 < Wl;
            bool h1ok = (h0 + 1) < Wl;
            bool w0ok = w0i < Wl;
            bool w1ok = (w0i + 1) < Wl;

            int idx = ((h0 << sh) + w0i) << 8;

            float4 v00 = (h0ok && w0ok) ? *reinterpret_cast<const float4*>(vb + idx)                 : zero;
            float4 v01 = (h0ok && w1ok) ? *reinterpret_cast<const float4*>(vb + idx + EMB)           : zero;
            float4 v10 = (h1ok && w0ok) ? *reinterpret_cast<const float4*>(vb + idx + rowStep)       : zero;
            float4 v11 = (h1ok && w1ok) ? *reinterpret_cast<const float4*>(vb + idx + rowStep + EMB) : zero;

            float4 top, bot;
            top.x = v00.x + fw * (v01.x - v00.x);
            top.y = v00.y + fw * (v01.y - v00.y);
            top.z = v00.z + fw * (v01.z - v00.z);
            top.w = v00.w + fw * (v01.w - v00.w);
            bot.x = v10.x + fw * (v11.x - v10.x);
            bot.y = v10.y + fw * (v11.y - v10.y);
            bot.z = v10.z + fw * (v11.z - v10.z);
            bot.w = v10.w + fw * (v11.w - v10.w);
            acc.x += aw * (top.x + fh * (bot.x - top.x));
            acc.y += aw * (top.y + fh * (bot.y - top.y));
            acc.z += aw * (top.z + fh * (bot.z - top.z));
            acc.w += aw * (top.w + fh * (bot.w - top.w));
        }
    }

    split_store4(acc, g_shi, g_slo, q * EMB + h * HD + lg * 4);
}

// ---------------------------------------------------------------------------
extern "C" void kernel_launch(void* const* d_in, const int* in_sizes, int n_in,
                              void* d_out, int out_size)
{
    const float* query  = (const float*)d_in[0];
    const float* qpos   = (const float*)d_in[1];
    const int*   qbo    = (const int*)  d_in[2];
    const float* fm     = (const float*)d_in[3];
    // d_in[4] = level_spatial_shapes (compile-time constants here)
    const int*   qlvl   = (const int*)  d_in[5];
    const float* W_off  = (const float*)d_in[6];
    const float* b_off  = (const float*)d_in[7];
    const float* W_attn = (const float*)d_in[8];
    const float* b_attn = (const float*)d_in[9];
    const float* W_val  = (const float*)d_in[10];
    const float* b_val  = (const float*)d_in[11];
    const float* W_out  = (const float*)d_in[12];
    const float* b_out  = (const float*)d_in[13];
    float* out = (float*)d_out;

    cudaFuncSetAttribute(mma_fused_kernel, cudaFuncAttributeMaxDynamicSharedMemorySize, SM_TOT);
    cudaFuncSetAttribute(mma_out_kernel,   cudaFuncAttributeMaxDynamicSharedMemorySize, SM_TOT);

    // 1) fp32 -> bf16 hi/lo splits (query, gathered fm rows, transposed weights)
    split_all_kernel<<<NB_IN + 896, 256>>>(query, fm, W_val, W_off, W_attn, W_out);
    // 2) tensor-core MMAs: values projection + offsets + attn logits (N-sliced)
    mma_fused_kernel<<<dim3(NQ / 128, 10), 256, SM_TOT>>>(b_val, b_off, b_attn);
    // 3) softmax + bilinear sampling + head-weighted accumulation (writes split)
    sample_kernel<<<NQ / 4, 256>>>(qpos, qlvl, qbo);
    // 4) output projection MMA -> d_out (N-sliced)
    mma_out_kernel<<<dim3(NQ / 128, 4), 256, SM_TOT>>>(b_out, out);
}